// round 14
// baseline (speedup 1.0000x reference)
#include <cuda_runtime.h>
#include <cuda_fp16.h>
#include <cstdint>

#define D_IN  128
#define D_HID 128
#define D_OUT 64
#define MAXN  100000
#define MAXE  1600000
#define SCAN_TILE 1024
#define MAX_TILES ((MAXN + SCAN_TILE - 1) / SCAN_TILE)   // 98
#define TS_TOTAL 0x40000000
#define TS_DONE  0x20000000

// ---- scratch ----
__device__ __half g_h1s[MAXN * D_HID];   // x@W1 (UNscaled), fp16
__device__ __half g_agg1[MAXN * D_HID];  // pull-aggregated layer-1 (fp16)
__device__ __half g_h2s[MAXN * D_OUT];   // (h1@W2)*dinv, fp16
__device__ float  g_dinv[MAXN];
__device__ int    g_deg[MAXN];
__device__ int    g_rowptr[MAXN];
__device__ int    g_rank[MAXE];          // edge rank within dst bucket
__device__ int    g_tilesum[MAX_TILES];
__device__ int    g_csrsrc[MAXE];

// ================= degree (saves per-edge rank) =================
__global__ void zero_deg_kernel(int n) {
    int i = blockIdx.x * blockDim.x + threadIdx.x;
    if (i < n) g_deg[i] = 0;
    if (i < MAX_TILES) g_tilesum[i] = 0;
}
__global__ void deg_kernel(const int* __restrict__ dst, int E) {
    int e = blockIdx.x * blockDim.x + threadIdx.x;
    if (e < E) g_rank[e] = atomicAdd(&g_deg[dst[e]], 1);
}

// ============ fused scan + fill (one kernel, grid barrier) ==============
// Phase 1: per-tile exclusive scan, decoupled lookback, write rowptr/dinv,
//          publish DONE after threadfence.
// Phase 2: all blocks wait for all DONE flags, then grid-stride fill.
// 98 blocks, all resident; lookback waits only on lower bids -> no deadlock.
__global__ void __launch_bounds__(256)
scan_fill_kernel(const int* __restrict__ src, const int* __restrict__ dst,
                 int n, int ntiles, int E)
{
    __shared__ int wsum[8];
    __shared__ int wred[8];
    __shared__ int s_off;
    const int tid  = threadIdx.x;
    const int lane = tid & 31, wid = tid >> 5;
    const int b    = blockIdx.x;
    const int base = b * SCAN_TILE + tid * 4;

    int v0 = 0, v1 = 0, v2 = 0, v3 = 0;
    if (base + 0 < n) v0 = g_deg[base + 0];
    if (base + 1 < n) v1 = g_deg[base + 1];
    if (base + 2 < n) v2 = g_deg[base + 2];
    if (base + 3 < n) v3 = g_deg[base + 3];
    int tsum = v0 + v1 + v2 + v3;

    int x = tsum;
    #pragma unroll
    for (int o = 1; o < 32; o <<= 1) {
        int y = __shfl_up_sync(0xFFFFFFFFu, x, o);
        if (lane >= o) x += y;
    }
    if (lane == 31) wsum[wid] = x;
    __syncthreads();
    if (wid == 0 && lane < 8) {
        int w = wsum[lane];
        #pragma unroll
        for (int o = 1; o < 8; o <<= 1) {
            int y = __shfl_up_sync(0xFFu, w, o);
            if (lane >= o) w += y;
        }
        wsum[lane] = w;
    }
    __syncthreads();
    const int warp_off = (wid == 0) ? 0 : wsum[wid - 1];
    const int excl = warp_off + x - tsum;
    const int total = wsum[7];

    // publish this tile's total
    if (tid == 0) atomicOr(&g_tilesum[b], total | TS_TOTAL);

    // lookback: thread tid<b spins for predecessor totals
    int contrib = 0;
    if (tid < b) {
        int t;
        do { t = atomicAdd(&g_tilesum[tid], 0); } while (!(t & TS_TOTAL));
        contrib = t & 0x1FFFFFFF;
    }
    #pragma unroll
    for (int o = 16; o > 0; o >>= 1)
        contrib += __shfl_down_sync(0xFFFFFFFFu, contrib, o);
    if (lane == 0) wred[wid] = contrib;
    __syncthreads();
    if (tid == 0)
        s_off = wred[0] + wred[1] + wred[2] + wred[3]
              + wred[4] + wred[5] + wred[6] + wred[7];
    __syncthreads();
    const int off = s_off;

    int r = off + excl;
    if (base + 0 < n) { g_rowptr[base+0] = r;          g_dinv[base+0] = rsqrtf((float)(v0+1)); }
    if (base + 1 < n) { g_rowptr[base+1] = r+v0;       g_dinv[base+1] = rsqrtf((float)(v1+1)); }
    if (base + 2 < n) { g_rowptr[base+2] = r+v0+v1;    g_dinv[base+2] = rsqrtf((float)(v2+1)); }
    if (base + 3 < n) { g_rowptr[base+3] = r+v0+v1+v2; g_dinv[base+3] = rsqrtf((float)(v3+1)); }

    // publish DONE (rowptr for this tile globally visible)
    __threadfence();
    __syncthreads();
    if (tid == 0) atomicOr(&g_tilesum[b], TS_DONE);

    // grid barrier: wait for ALL tiles' DONE
    if (tid < ntiles) {
        int t;
        do { t = atomicAdd(&g_tilesum[tid], 0); } while (!(t & TS_DONE));
    }
    __syncthreads();
    __threadfence();

    // phase 2: grid-stride fill (atomic-free)
    const int stride = gridDim.x * 256;
    for (int e = b * 256 + tid; e < E; e += stride) {
        int pos = g_rowptr[dst[e]] + g_rank[e];
        g_csrsrc[pos] = src[e];
    }
}

// ================= fp16 helpers =================
__device__ __forceinline__ uint32_t pack2(float a, float b) {
    __half2 h = __floats2half2_rn(a, b);
    return *reinterpret_cast<uint32_t*>(&h);
}
__device__ __forceinline__ void mma_f16(float* c, const uint32_t* a,
                                        const uint32_t* b) {
    asm volatile(
        "mma.sync.aligned.m16n8k16.row.col.f32.f16.f16.f32 "
        "{%0,%1,%2,%3}, {%4,%5,%6,%7}, {%8,%9}, {%0,%1,%2,%3};"
        : "+f"(c[0]), "+f"(c[1]), "+f"(c[2]), "+f"(c[3])
        : "r"(a[0]), "r"(a[1]), "r"(a[2]), "r"(a[3]), "r"(b[0]), "r"(b[1]));
}
__device__ __forceinline__ float4 h4_to_f4(uint2 u) {
    __half2 h0 = *reinterpret_cast<__half2*>(&u.x);
    __half2 h1 = *reinterpret_cast<__half2*>(&u.y);
    float2 f0 = __half22float2(h0);
    float2 f1 = __half22float2(h1);
    return make_float4(f0.x, f0.y, f1.x, f1.y);
}

// ============ GEMM1: h1s = fp16{ x @ W1 }  (fp16 m16n8k16) ==============
__global__ void __launch_bounds__(256)
gemm1_kernel(const float* __restrict__ x, const float* __restrict__ W1,
             __half* __restrict__ out, int M)
{
    constexpr int N = 128, K = 128, PA = 68, PB = 136, WN = 64, NT = 8;
    extern __shared__ uint32_t smem[];
    uint32_t* As = smem;             // 128 x PA
    uint32_t* Bs = smem + 128 * PA;  // 64 x PB

    const int tid    = threadIdx.x;
    const int warp   = tid >> 5;
    const int lane   = tid & 31;
    const int warp_m = warp & 3;
    const int warp_n = warp >> 2;
    const int bm     = blockIdx.x * 128;

    #pragma unroll
    for (int it = 0; it < 16; it++) {
        int idx = tid + it * 256;
        int row = idx >> 5;
        int g   = idx & 31;
        int grow = bm + row;
        float4 v = make_float4(0.f, 0.f, 0.f, 0.f);
        if (grow < M)
            v = *reinterpret_cast<const float4*>(&x[(size_t)grow * K + g * 4]);
        uint2 u = make_uint2(pack2(v.x, v.y), pack2(v.z, v.w));
        *reinterpret_cast<uint2*>(&As[row * PA + g * 2]) = u;
    }
    #pragma unroll
    for (int it = 0; it < 8; it++) {
        int idx = tid + it * 256;
        int k2  = idx >> 5;
        int nq  = idx & 31;
        float4 r0 = *reinterpret_cast<const float4*>(&W1[(size_t)(2 * k2) * N + nq * 4]);
        float4 r1 = *reinterpret_cast<const float4*>(&W1[(size_t)(2 * k2 + 1) * N + nq * 4]);
        uint4 u = make_uint4(pack2(r0.x, r1.x), pack2(r0.y, r1.y),
                             pack2(r0.z, r1.z), pack2(r0.w, r1.w));
        *reinterpret_cast<uint4*>(&Bs[k2 * PB + nq * 4]) = u;
    }
    __syncthreads();

    float c[2][NT][4];
    #pragma unroll
    for (int mt = 0; mt < 2; mt++)
        #pragma unroll
        for (int nt = 0; nt < NT; nt++)
            #pragma unroll
            for (int j = 0; j < 4; j++) c[mt][nt][j] = 0.f;

    const int lq = lane >> 2;
    const int lr = lane & 3;

    #pragma unroll
    for (int ks = 0; ks < 8; ks++) {
        const int k20 = ks * 8 + lr;
        uint32_t a[2][4];
        #pragma unroll
        for (int mt = 0; mt < 2; mt++) {
            int r = warp_m * 32 + mt * 16 + lq;
            a[mt][0] = As[r * PA + k20];
            a[mt][1] = As[(r + 8) * PA + k20];
            a[mt][2] = As[r * PA + k20 + 4];
            a[mt][3] = As[(r + 8) * PA + k20 + 4];
        }
        uint32_t b[NT][2];
        #pragma unroll
        for (int nt = 0; nt < NT; nt++) {
            int n = warp_n * WN + nt * 8 + lq;
            b[nt][0] = Bs[k20 * PB + n];
            b[nt][1] = Bs[(k20 + 4) * PB + n];
        }
        #pragma unroll
        for (int mt = 0; mt < 2; mt++)
            #pragma unroll
            for (int nt = 0; nt < NT; nt++)
                mma_f16(c[mt][nt], a[mt], b[nt]);
    }

    #pragma unroll
    for (int mt = 0; mt < 2; mt++) {
        int r0 = bm + warp_m * 32 + mt * 16 + lq;
        int r1 = r0 + 8;
        #pragma unroll
        for (int nt = 0; nt < NT; nt++) {
            int n = warp_n * WN + nt * 8 + 2 * lr;
            if (r0 < M) {
                __half2 h = __floats2half2_rn(c[mt][nt][0], c[mt][nt][1]);
                *reinterpret_cast<__half2*>(&out[(size_t)r0 * N + n]) = h;
            }
            if (r1 < M) {
                __half2 h = __floats2half2_rn(c[mt][nt][2], c[mt][nt][3]);
                *reinterpret_cast<__half2*>(&out[(size_t)r1 * N + n]) = h;
            }
        }
    }
}

// ============ gather128 (node range [off, off+cnt)) =====================
__global__ void __launch_bounds__(256)
gather128_kernel(const __half* __restrict__ hs, const float* __restrict__ dinv,
                 __half* __restrict__ agg, int off, int cnt)
{
    int gw = (blockIdx.x * blockDim.x + threadIdx.x) >> 5;
    int lane = threadIdx.x & 31;
    if (gw >= cnt) return;
    const int v   = off + gw;
    const int beg = g_rowptr[v];
    const int end = beg + g_deg[v];
    const int col = lane * 4;

    float dv = dinv[v];
    float4 t = h4_to_f4(*reinterpret_cast<const uint2*>(&hs[(size_t)v * D_HID + col]));
    float4 acc = make_float4(dv * t.x, dv * t.y, dv * t.z, dv * t.w);
    int e = beg;
    for (; e + 8 <= end; e += 8) {
        int myi = 0; float myd = 0.f;
        if (lane < 8) {
            myi = __ldg(&g_csrsrc[e + lane]);
            myd = __ldg(&dinv[myi]);
        }
        #pragma unroll
        for (int j = 0; j < 8; j++) {
            int   s = __shfl_sync(0xFFFFFFFFu, myi, j);
            float d = __shfl_sync(0xFFFFFFFFu, myd, j);
            float4 tt = h4_to_f4(*reinterpret_cast<const uint2*>(&hs[(size_t)s * D_HID + col]));
            acc.x = fmaf(d, tt.x, acc.x);
            acc.y = fmaf(d, tt.y, acc.y);
            acc.z = fmaf(d, tt.z, acc.z);
            acc.w = fmaf(d, tt.w, acc.w);
        }
    }
    for (; e < end; e++) {
        int s = __ldg(&g_csrsrc[e]);
        float d = __ldg(&dinv[s]);
        float4 tt = h4_to_f4(*reinterpret_cast<const uint2*>(&hs[(size_t)s * D_HID + col]));
        acc.x = fmaf(d, tt.x, acc.x);
        acc.y = fmaf(d, tt.y, acc.y);
        acc.z = fmaf(d, tt.z, acc.z);
        acc.w = fmaf(d, tt.w, acc.w);
    }
    uint2 u = make_uint2(pack2(acc.x, acc.y), pack2(acc.z, acc.w));
    *reinterpret_cast<uint2*>(&agg[(size_t)v * D_HID + col]) = u;
}

// ============ GEMM2 (row range starts at roff): ==========================
// h2s = fp16{ relu(agg*dinv+b1) @ W2 * dinv }
__global__ void __launch_bounds__(256)
gemm2_kernel(const __half* __restrict__ A, const float* __restrict__ W2,
             const float* __restrict__ dinv, const float* __restrict__ b1,
             __half* __restrict__ out, int roff, int M)
{
    constexpr int N = 64, K = 128, PA = 68, PB = 72, WN = 32, NT = 4;
    extern __shared__ uint32_t smem[];
    uint32_t* As = smem;             // 128 x PA
    uint32_t* Bs = smem + 128 * PA;  // 64 x PB

    const int tid    = threadIdx.x;
    const int warp   = tid >> 5;
    const int lane   = tid & 31;
    const int warp_m = warp & 3;
    const int warp_n = warp >> 2;
    const int bm     = roff + blockIdx.x * 128;

    #pragma unroll
    for (int it = 0; it < 16; it++) {
        int idx = tid + it * 256;
        int row = idx >> 5;
        int g   = idx & 31;
        int grow = bm + row;
        float4 v = make_float4(0.f, 0.f, 0.f, 0.f);
        if (grow < M) {
            v = h4_to_f4(*reinterpret_cast<const uint2*>(&A[(size_t)grow * K + g * 4]));
            float s = dinv[grow];
            float4 bb = *reinterpret_cast<const float4*>(&b1[g * 4]);
            v.x = fmaxf(fmaf(v.x, s, bb.x), 0.f);
            v.y = fmaxf(fmaf(v.y, s, bb.y), 0.f);
            v.z = fmaxf(fmaf(v.z, s, bb.z), 0.f);
            v.w = fmaxf(fmaf(v.w, s, bb.w), 0.f);
        }
        uint2 u = make_uint2(pack2(v.x, v.y), pack2(v.z, v.w));
        *reinterpret_cast<uint2*>(&As[row * PA + g * 2]) = u;
    }
    #pragma unroll
    for (int it = 0; it < 4; it++) {
        int idx = tid + it * 256;
        int k2  = idx >> 4;
        int nq  = idx & 15;
        float4 r0 = *reinterpret_cast<const float4*>(&W2[(size_t)(2 * k2) * N + nq * 4]);
        float4 r1 = *reinterpret_cast<const float4*>(&W2[(size_t)(2 * k2 + 1) * N + nq * 4]);
        uint4 u = make_uint4(pack2(r0.x, r1.x), pack2(r0.y, r1.y),
                             pack2(r0.z, r1.z), pack2(r0.w, r1.w));
        *reinterpret_cast<uint4*>(&Bs[k2 * PB + nq * 4]) = u;
    }
    __syncthreads();

    float c[2][NT][4];
    #pragma unroll
    for (int mt = 0; mt < 2; mt++)
        #pragma unroll
        for (int nt = 0; nt < NT; nt++)
            #pragma unroll
            for (int j = 0; j < 4; j++) c[mt][nt][j] = 0.f;

    const int lq = lane >> 2;
    const int lr = lane & 3;

    #pragma unroll
    for (int ks = 0; ks < 8; ks++) {
        const int k20 = ks * 8 + lr;
        uint32_t a[2][4];
        #pragma unroll
        for (int mt = 0; mt < 2; mt++) {
            int r = warp_m * 32 + mt * 16 + lq;
            a[mt][0] = As[r * PA + k20];
            a[mt][1] = As[(r + 8) * PA + k20];
            a[mt][2] = As[r * PA + k20 + 4];
            a[mt][3] = As[(r + 8) * PA + k20 + 4];
        }
        uint32_t b[NT][2];
        #pragma unroll
        for (int nt = 0; nt < NT; nt++) {
            int n = warp_n * WN + nt * 8 + lq;
            b[nt][0] = Bs[k20 * PB + n];
            b[nt][1] = Bs[(k20 + 4) * PB + n];
        }
        #pragma unroll
        for (int mt = 0; mt < 2; mt++)
            #pragma unroll
            for (int nt = 0; nt < NT; nt++)
                mma_f16(c[mt][nt], a[mt], b[nt]);
    }

    #pragma unroll
    for (int mt = 0; mt < 2; mt++) {
        int r0 = bm + warp_m * 32 + mt * 16 + lq;
        int r1 = r0 + 8;
        float s0 = (r0 < M) ? dinv[r0] : 0.f;
        float s1 = (r1 < M) ? dinv[r1] : 0.f;
        #pragma unroll
        for (int nt = 0; nt < NT; nt++) {
            int n = warp_n * WN + nt * 8 + 2 * lr;
            if (r0 < M) {
                __half2 h = __floats2half2_rn(c[mt][nt][0] * s0, c[mt][nt][1] * s0);
                *reinterpret_cast<__half2*>(&out[(size_t)r0 * N + n]) = h;
            }
            if (r1 < M) {
                __half2 h = __floats2half2_rn(c[mt][nt][2] * s1, c[mt][nt][3] * s1);
                *reinterpret_cast<__half2*>(&out[(size_t)r1 * N + n]) = h;
            }
        }
    }
}

// ============ gather64: final pull-aggregate + bias -> out (fp32) =======
__global__ void __launch_bounds__(256)
gather64_out_kernel(const __half* __restrict__ hs, const float* __restrict__ dinv,
                    const float* __restrict__ b2, float* __restrict__ out, int M)
{
    int gw = (blockIdx.x * blockDim.x + threadIdx.x) >> 5;
    int lane = threadIdx.x & 31;
    if (gw >= M) return;
    const int v   = gw;
    const int beg = g_rowptr[v];
    const int end = beg + g_deg[v];
    const int col = lane * 2;

    float2 acc = __half22float2(*reinterpret_cast<const __half2*>(&hs[(size_t)v * D_OUT + col]));
    int e = beg;
    for (; e + 8 <= end; e += 8) {
        int myi = 0;
        if (lane < 8) myi = __ldg(&g_csrsrc[e + lane]);
        #pragma unroll
        for (int j = 0; j < 8; j++) {
            int s = __shfl_sync(0xFFFFFFFFu, myi, j);
            float2 t = __half22float2(*reinterpret_cast<const __half2*>(&hs[(size_t)s * D_OUT + col]));
            acc.x += t.x;
            acc.y += t.y;
        }
    }
    for (; e < end; e++) {
        int s = __ldg(&g_csrsrc[e]);
        float2 t = __half22float2(*reinterpret_cast<const __half2*>(&hs[(size_t)s * D_OUT + col]));
        acc.x += t.x; acc.y += t.y;
    }
    float s = dinv[v];
    float2 bb = *reinterpret_cast<const float2*>(&b2[col]);
    float2 r = make_float2(fmaf(acc.x, s, bb.x), fmaf(acc.y, s, bb.y));
    *reinterpret_cast<float2*>(&out[(size_t)v * D_OUT + col]) = r;
}

// ================= launch =================
extern "C" void kernel_launch(void* const* d_in, const int* in_sizes, int n_in,
                              void* d_out, int out_size)
{
    const float* x  = (const float*)d_in[0];
    const int*   ei = (const int*)  d_in[1];
    const float* W1 = (const float*)d_in[2];
    const float* b1 = (const float*)d_in[3];
    const float* W2 = (const float*)d_in[4];
    const float* b2 = (const float*)d_in[5];
    float* out = (float*)d_out;

    const int M = in_sizes[0] / D_IN;
    const int E = in_sizes[1] / 2;
    const int* src = ei;
    const int* dst = ei + E;

    __half *p_h1s, *p_agg1, *p_h2s;
    float *p_dinv;
    cudaGetSymbolAddress((void**)&p_h1s,  g_h1s);
    cudaGetSymbolAddress((void**)&p_agg1, g_agg1);
    cudaGetSymbolAddress((void**)&p_h2s,  g_h2s);
    cudaGetSymbolAddress((void**)&p_dinv, g_dinv);

    static cudaStream_t s2 = nullptr;
    static cudaEvent_t evFork = nullptr, evJoin = nullptr, evA = nullptr, evB = nullptr;
    if (s2 == nullptr) {
        cudaStreamCreateWithFlags(&s2, cudaStreamNonBlocking);
        cudaEventCreateWithFlags(&evFork, cudaEventDisableTiming);
        cudaEventCreateWithFlags(&evJoin, cudaEventDisableTiming);
        cudaEventCreateWithFlags(&evA, cudaEventDisableTiming);
        cudaEventCreateWithFlags(&evB, cudaEventDisableTiming);
    }

    const int T = 256;
    const int smem1 = (128 * 68 + 64 * 136) * 4;   // 69632
    const int smem2 = (128 * 68 + 64 * 72) * 4;    // 53248
    cudaFuncSetAttribute(gemm1_kernel,
                         cudaFuncAttributeMaxDynamicSharedMemorySize, smem1);
    cudaFuncSetAttribute(gemm2_kernel,
                         cudaFuncAttributeMaxDynamicSharedMemorySize, smem2);

    const int ntiles = (M + SCAN_TILE - 1) / SCAN_TILE;
    const int nblk = (M + 127) / 128;

    // chunk split for gather128/gemm2 pipelining
    const int nbA = nblk / 2;
    const int M0  = nbA * 128;         // chunk A rows
    const int cntB = M - M0;           // chunk B rows
    const int nbB = nblk - nbA;
    const int gbA = (M0 + 7) / 8;
    const int gbB = (cntB + 7) / 8;

    // ---- fork: CSR chain on s2, GEMM1 on main ----
    cudaEventRecord(evFork, 0);
    cudaStreamWaitEvent(s2, evFork, 0);

    zero_deg_kernel<<<(M + T - 1) / T, T, 0, s2>>>(M);
    deg_kernel<<<(E + T - 1) / T, T, 0, s2>>>(dst, E);
    scan_fill_kernel<<<ntiles, 256, 0, s2>>>(src, dst, M, ntiles, E);
    cudaEventRecord(evJoin, s2);

    // main: layer-1 GEMM
    gemm1_kernel<<<nblk, 256, smem1>>>(x, W1, p_h1s, M);

    cudaStreamWaitEvent(0, evJoin, 0);

    // ---- pipelined gather128 / gemm2 ----
    // main: gather A, then gemm2(A) overlapping s2: gather B
    gather128_kernel<<<gbA, 256>>>(p_h1s, p_dinv, p_agg1, 0, M0);
    cudaEventRecord(evA, 0);
    cudaStreamWaitEvent(s2, evA, 0);
    gather128_kernel<<<gbB, 256, 0, s2>>>(p_h1s, p_dinv, p_agg1, M0, cntB);
    cudaEventRecord(evB, s2);

    gemm2_kernel<<<nbA, 256, smem2>>>(p_agg1, W2, p_dinv, b1, p_h2s, 0, M);

    cudaStreamWaitEvent(0, evB, 0);
    gemm2_kernel<<<nbB, 256, smem2>>>(p_agg1, W2, p_dinv, b1, p_h2s, M0, M);

    // final pull-aggregate + bias -> out
    gather64_out_kernel<<<(M + 7) / 8, 256>>>(p_h2s, p_dinv, b2, out, M);
}

// round 15
// speedup vs baseline: 1.2903x; 1.2903x over previous
#include <cuda_runtime.h>
#include <cuda_fp16.h>
#include <cstdint>

#define D_IN  128
#define D_HID 128
#define D_OUT 64
#define MAXN  100000
#define MAXE  1600000
#define SCAN_TILE 1024
#define MAX_TILES ((MAXN + SCAN_TILE - 1) / SCAN_TILE)   // 98
#define TS_FLAG 0x40000000

// ---- scratch ----
__device__ __half g_h1s[MAXN * D_HID];   // x@W1 (UNscaled), fp16
__device__ __half g_agg1[MAXN * D_HID];  // pull-aggregated layer-1 (fp16)
__device__ __half g_h2s[MAXN * D_OUT];   // (h1@W2)*dinv, fp16
__device__ float  g_dinv[MAXN];
__device__ int    g_deg[MAXN];
__device__ int    g_rowptr[MAXN];
__device__ int    g_rank[MAXE];          // edge rank within dst bucket
__device__ int    g_tilesum[MAX_TILES];
__device__ int    g_csrsrc[MAXE];

// ================= degree (saves per-edge rank) =================
__global__ void deg_kernel(const int* __restrict__ dst, int E) {
    int e = blockIdx.x * blockDim.x + threadIdx.x;
    if (e < E) g_rank[e] = atomicAdd(&g_deg[dst[e]], 1);
}

// ============ fused single-pass scan =====================================
// Per-tile exclusive scan in registers; publish tile total with FLAG;
// spin-wait predecessors; write rowptr/dinv. 98 blocks, all resident;
// block b only waits on lower bids -> no deadlock.
__global__ void __launch_bounds__(256) scan_fused_kernel(int n) {
    __shared__ int wsum[8];
    __shared__ int wred[8];
    __shared__ int s_off;
    const int tid  = threadIdx.x;
    const int lane = tid & 31, wid = tid >> 5;
    const int b    = blockIdx.x;
    const int base = b * SCAN_TILE + tid * 4;

    int v0 = 0, v1 = 0, v2 = 0, v3 = 0;
    if (base + 0 < n) v0 = g_deg[base + 0];
    if (base + 1 < n) v1 = g_deg[base + 1];
    if (base + 2 < n) v2 = g_deg[base + 2];
    if (base + 3 < n) v3 = g_deg[base + 3];
    int tsum = v0 + v1 + v2 + v3;

    int x = tsum;
    #pragma unroll
    for (int o = 1; o < 32; o <<= 1) {
        int y = __shfl_up_sync(0xFFFFFFFFu, x, o);
        if (lane >= o) x += y;
    }
    if (lane == 31) wsum[wid] = x;
    __syncthreads();
    if (wid == 0 && lane < 8) {
        int w = wsum[lane];
        #pragma unroll
        for (int o = 1; o < 8; o <<= 1) {
            int y = __shfl_up_sync(0xFFu, w, o);
            if (lane >= o) w += y;
        }
        wsum[lane] = w;
    }
    __syncthreads();
    const int warp_off = (wid == 0) ? 0 : wsum[wid - 1];
    const int excl = warp_off + x - tsum;
    const int total = wsum[7];

    if (tid == 0) atomicExch(&g_tilesum[b], total | TS_FLAG);

    int contrib = 0;
    if (tid < b) {
        int t;
        do { t = atomicAdd(&g_tilesum[tid], 0); } while (!(t & TS_FLAG));
        contrib = t & ~TS_FLAG;
    }
    #pragma unroll
    for (int o = 16; o > 0; o >>= 1)
        contrib += __shfl_down_sync(0xFFFFFFFFu, contrib, o);
    if (lane == 0) wred[wid] = contrib;
    __syncthreads();
    if (tid == 0)
        s_off = wred[0] + wred[1] + wred[2] + wred[3]
              + wred[4] + wred[5] + wred[6] + wred[7];
    __syncthreads();
    const int off = s_off;

    int r = off + excl;
    if (base + 0 < n) { g_rowptr[base+0] = r;          g_dinv[base+0] = rsqrtf((float)(v0+1)); }
    if (base + 1 < n) { g_rowptr[base+1] = r+v0;       g_dinv[base+1] = rsqrtf((float)(v1+1)); }
    if (base + 2 < n) { g_rowptr[base+2] = r+v0+v1;    g_dinv[base+2] = rsqrtf((float)(v2+1)); }
    if (base + 3 < n) { g_rowptr[base+3] = r+v0+v1+v2; g_dinv[base+3] = rsqrtf((float)(v3+1)); }
}

// ============ fill (atomic-free): pos = rowptr[dst] + rank ==============
__global__ void fill_kernel(const int* __restrict__ src,
                            const int* __restrict__ dst, int E) {
    int e = blockIdx.x * blockDim.x + threadIdx.x;
    if (e < E) {
        int pos = g_rowptr[dst[e]] + g_rank[e];
        g_csrsrc[pos] = src[e];
    }
}

// ================= fp16 helpers =================
__device__ __forceinline__ uint32_t pack2(float a, float b) {
    __half2 h = __floats2half2_rn(a, b);
    return *reinterpret_cast<uint32_t*>(&h);
}
__device__ __forceinline__ void mma_f16(float* c, const uint32_t* a,
                                        const uint32_t* b) {
    asm volatile(
        "mma.sync.aligned.m16n8k16.row.col.f32.f16.f16.f32 "
        "{%0,%1,%2,%3}, {%4,%5,%6,%7}, {%8,%9}, {%0,%1,%2,%3};"
        : "+f"(c[0]), "+f"(c[1]), "+f"(c[2]), "+f"(c[3])
        : "r"(a[0]), "r"(a[1]), "r"(a[2]), "r"(a[3]), "r"(b[0]), "r"(b[1]));
}
__device__ __forceinline__ float4 h4_to_f4(uint2 u) {
    __half2 h0 = *reinterpret_cast<__half2*>(&u.x);
    __half2 h1 = *reinterpret_cast<__half2*>(&u.y);
    float2 f0 = __half22float2(h0);
    float2 f1 = __half22float2(h1);
    return make_float4(f0.x, f0.y, f1.x, f1.y);
}

// ============ GEMM1: h1s = fp16{ x @ W1 }  (fp16 m16n8k16) ==============
__global__ void __launch_bounds__(256)
gemm1_kernel(const float* __restrict__ x, const float* __restrict__ W1,
             __half* __restrict__ out, int M)
{
    constexpr int N = 128, K = 128, PA = 68, PB = 136, WN = 64, NT = 8;
    extern __shared__ uint32_t smem[];
    uint32_t* As = smem;             // 128 x PA
    uint32_t* Bs = smem + 128 * PA;  // 64 x PB

    const int tid    = threadIdx.x;
    const int warp   = tid >> 5;
    const int lane   = tid & 31;
    const int warp_m = warp & 3;
    const int warp_n = warp >> 2;
    const int bm     = blockIdx.x * 128;

    #pragma unroll
    for (int it = 0; it < 16; it++) {
        int idx = tid + it * 256;
        int row = idx >> 5;
        int g   = idx & 31;
        int grow = bm + row;
        float4 v = make_float4(0.f, 0.f, 0.f, 0.f);
        if (grow < M)
            v = *reinterpret_cast<const float4*>(&x[(size_t)grow * K + g * 4]);
        uint2 u = make_uint2(pack2(v.x, v.y), pack2(v.z, v.w));
        *reinterpret_cast<uint2*>(&As[row * PA + g * 2]) = u;
    }
    #pragma unroll
    for (int it = 0; it < 8; it++) {
        int idx = tid + it * 256;
        int k2  = idx >> 5;
        int nq  = idx & 31;
        float4 r0 = *reinterpret_cast<const float4*>(&W1[(size_t)(2 * k2) * N + nq * 4]);
        float4 r1 = *reinterpret_cast<const float4*>(&W1[(size_t)(2 * k2 + 1) * N + nq * 4]);
        uint4 u = make_uint4(pack2(r0.x, r1.x), pack2(r0.y, r1.y),
                             pack2(r0.z, r1.z), pack2(r0.w, r1.w));
        *reinterpret_cast<uint4*>(&Bs[k2 * PB + nq * 4]) = u;
    }
    __syncthreads();

    float c[2][NT][4];
    #pragma unroll
    for (int mt = 0; mt < 2; mt++)
        #pragma unroll
        for (int nt = 0; nt < NT; nt++)
            #pragma unroll
            for (int j = 0; j < 4; j++) c[mt][nt][j] = 0.f;

    const int lq = lane >> 2;
    const int lr = lane & 3;

    #pragma unroll
    for (int ks = 0; ks < 8; ks++) {
        const int k20 = ks * 8 + lr;
        uint32_t a[2][4];
        #pragma unroll
        for (int mt = 0; mt < 2; mt++) {
            int r = warp_m * 32 + mt * 16 + lq;
            a[mt][0] = As[r * PA + k20];
            a[mt][1] = As[(r + 8) * PA + k20];
            a[mt][2] = As[r * PA + k20 + 4];
            a[mt][3] = As[(r + 8) * PA + k20 + 4];
        }
        uint32_t b[NT][2];
        #pragma unroll
        for (int nt = 0; nt < NT; nt++) {
            int n = warp_n * WN + nt * 8 + lq;
            b[nt][0] = Bs[k20 * PB + n];
            b[nt][1] = Bs[(k20 + 4) * PB + n];
        }
        #pragma unroll
        for (int mt = 0; mt < 2; mt++)
            #pragma unroll
            for (int nt = 0; nt < NT; nt++)
                mma_f16(c[mt][nt], a[mt], b[nt]);
    }

    #pragma unroll
    for (int mt = 0; mt < 2; mt++) {
        int r0 = bm + warp_m * 32 + mt * 16 + lq;
        int r1 = r0 + 8;
        #pragma unroll
        for (int nt = 0; nt < NT; nt++) {
            int n = warp_n * WN + nt * 8 + 2 * lr;
            if (r0 < M) {
                __half2 h = __floats2half2_rn(c[mt][nt][0], c[mt][nt][1]);
                *reinterpret_cast<__half2*>(&out[(size_t)r0 * N + n]) = h;
            }
            if (r1 < M) {
                __half2 h = __floats2half2_rn(c[mt][nt][2], c[mt][nt][3]);
                *reinterpret_cast<__half2*>(&out[(size_t)r1 * N + n]) = h;
            }
        }
    }
}

// ============ gather128: agg[v] = dinv[v]*h1s[v] + sum dinv[s]*h1s[s] ===
__global__ void __launch_bounds__(256)
gather128_kernel(const __half* __restrict__ hs, const float* __restrict__ dinv,
                 __half* __restrict__ agg, int M)
{
    int gw = (blockIdx.x * blockDim.x + threadIdx.x) >> 5;
    int lane = threadIdx.x & 31;
    if (gw >= M) return;
    const int v   = gw;
    const int beg = g_rowptr[v];
    const int end = beg + g_deg[v];
    const int col = lane * 4;

    float dv = dinv[v];
    float4 t = h4_to_f4(*reinterpret_cast<const uint2*>(&hs[(size_t)v * D_HID + col]));
    float4 acc = make_float4(dv * t.x, dv * t.y, dv * t.z, dv * t.w);
    int e = beg;
    for (; e + 8 <= end; e += 8) {
        int myi = 0; float myd = 0.f;
        if (lane < 8) {
            myi = __ldg(&g_csrsrc[e + lane]);
            myd = __ldg(&dinv[myi]);
        }
        #pragma unroll
        for (int j = 0; j < 8; j++) {
            int   s = __shfl_sync(0xFFFFFFFFu, myi, j);
            float d = __shfl_sync(0xFFFFFFFFu, myd, j);
            float4 tt = h4_to_f4(*reinterpret_cast<const uint2*>(&hs[(size_t)s * D_HID + col]));
            acc.x = fmaf(d, tt.x, acc.x);
            acc.y = fmaf(d, tt.y, acc.y);
            acc.z = fmaf(d, tt.z, acc.z);
            acc.w = fmaf(d, tt.w, acc.w);
        }
    }
    for (; e < end; e++) {
        int s = __ldg(&g_csrsrc[e]);
        float d = __ldg(&dinv[s]);
        float4 tt = h4_to_f4(*reinterpret_cast<const uint2*>(&hs[(size_t)s * D_HID + col]));
        acc.x = fmaf(d, tt.x, acc.x);
        acc.y = fmaf(d, tt.y, acc.y);
        acc.z = fmaf(d, tt.z, acc.z);
        acc.w = fmaf(d, tt.w, acc.w);
    }
    uint2 u = make_uint2(pack2(acc.x, acc.y), pack2(acc.z, acc.w));
    *reinterpret_cast<uint2*>(&agg[(size_t)v * D_HID + col]) = u;
}

// ============ GEMM2: h2s = fp16{ relu(agg*dinv+b1) @ W2 * dinv } ========
__global__ void __launch_bounds__(256)
gemm2_kernel(const __half* __restrict__ A, const float* __restrict__ W2,
             const float* __restrict__ dinv, const float* __restrict__ b1,
             __half* __restrict__ out, int M)
{
    constexpr int N = 64, K = 128, PA = 68, PB = 72, WN = 32, NT = 4;
    extern __shared__ uint32_t smem[];
    uint32_t* As = smem;             // 128 x PA
    uint32_t* Bs = smem + 128 * PA;  // 64 x PB

    const int tid    = threadIdx.x;
    const int warp   = tid >> 5;
    const int lane   = tid & 31;
    const int warp_m = warp & 3;
    const int warp_n = warp >> 2;
    const int bm     = blockIdx.x * 128;

    #pragma unroll
    for (int it = 0; it < 16; it++) {
        int idx = tid + it * 256;
        int row = idx >> 5;
        int g   = idx & 31;
        int grow = bm + row;
        float4 v = make_float4(0.f, 0.f, 0.f, 0.f);
        if (grow < M) {
            v = h4_to_f4(*reinterpret_cast<const uint2*>(&A[(size_t)grow * K + g * 4]));
            float s = dinv[grow];
            float4 bb = *reinterpret_cast<const float4*>(&b1[g * 4]);
            v.x = fmaxf(fmaf(v.x, s, bb.x), 0.f);
            v.y = fmaxf(fmaf(v.y, s, bb.y), 0.f);
            v.z = fmaxf(fmaf(v.z, s, bb.z), 0.f);
            v.w = fmaxf(fmaf(v.w, s, bb.w), 0.f);
        }
        uint2 u = make_uint2(pack2(v.x, v.y), pack2(v.z, v.w));
        *reinterpret_cast<uint2*>(&As[row * PA + g * 2]) = u;
    }
    #pragma unroll
    for (int it = 0; it < 4; it++) {
        int idx = tid + it * 256;
        int k2  = idx >> 4;
        int nq  = idx & 15;
        float4 r0 = *reinterpret_cast<const float4*>(&W2[(size_t)(2 * k2) * N + nq * 4]);
        float4 r1 = *reinterpret_cast<const float4*>(&W2[(size_t)(2 * k2 + 1) * N + nq * 4]);
        uint4 u = make_uint4(pack2(r0.x, r1.x), pack2(r0.y, r1.y),
                             pack2(r0.z, r1.z), pack2(r0.w, r1.w));
        *reinterpret_cast<uint4*>(&Bs[k2 * PB + nq * 4]) = u;
    }
    __syncthreads();

    float c[2][NT][4];
    #pragma unroll
    for (int mt = 0; mt < 2; mt++)
        #pragma unroll
        for (int nt = 0; nt < NT; nt++)
            #pragma unroll
            for (int j = 0; j < 4; j++) c[mt][nt][j] = 0.f;

    const int lq = lane >> 2;
    const int lr = lane & 3;

    #pragma unroll
    for (int ks = 0; ks < 8; ks++) {
        const int k20 = ks * 8 + lr;
        uint32_t a[2][4];
        #pragma unroll
        for (int mt = 0; mt < 2; mt++) {
            int r = warp_m * 32 + mt * 16 + lq;
            a[mt][0] = As[r * PA + k20];
            a[mt][1] = As[(r + 8) * PA + k20];
            a[mt][2] = As[r * PA + k20 + 4];
            a[mt][3] = As[(r + 8) * PA + k20 + 4];
        }
        uint32_t b[NT][2];
        #pragma unroll
        for (int nt = 0; nt < NT; nt++) {
            int n = warp_n * WN + nt * 8 + lq;
            b[nt][0] = Bs[k20 * PB + n];
            b[nt][1] = Bs[(k20 + 4) * PB + n];
        }
        #pragma unroll
        for (int mt = 0; mt < 2; mt++)
            #pragma unroll
            for (int nt = 0; nt < NT; nt++)
                mma_f16(c[mt][nt], a[mt], b[nt]);
    }

    #pragma unroll
    for (int mt = 0; mt < 2; mt++) {
        int r0 = bm + warp_m * 32 + mt * 16 + lq;
        int r1 = r0 + 8;
        float s0 = (r0 < M) ? dinv[r0] : 0.f;
        float s1 = (r1 < M) ? dinv[r1] : 0.f;
        #pragma unroll
        for (int nt = 0; nt < NT; nt++) {
            int n = warp_n * WN + nt * 8 + 2 * lr;
            if (r0 < M) {
                __half2 h = __floats2half2_rn(c[mt][nt][0] * s0, c[mt][nt][1] * s0);
                *reinterpret_cast<__half2*>(&out[(size_t)r0 * N + n]) = h;
            }
            if (r1 < M) {
                __half2 h = __floats2half2_rn(c[mt][nt][2] * s1, c[mt][nt][3] * s1);
                *reinterpret_cast<__half2*>(&out[(size_t)r1 * N + n]) = h;
            }
        }
    }
}

// ============ gather64: final pull-aggregate + bias -> out (fp32) =======
__global__ void __launch_bounds__(256)
gather64_out_kernel(const __half* __restrict__ hs, const float* __restrict__ dinv,
                    const float* __restrict__ b2, float* __restrict__ out, int M)
{
    int gw = (blockIdx.x * blockDim.x + threadIdx.x) >> 5;
    int lane = threadIdx.x & 31;
    if (gw >= M) return;
    const int v   = gw;
    const int beg = g_rowptr[v];
    const int end = beg + g_deg[v];
    const int col = lane * 2;

    float2 acc = __half22float2(*reinterpret_cast<const __half2*>(&hs[(size_t)v * D_OUT + col]));
    int e = beg;
    for (; e + 8 <= end; e += 8) {
        int myi = 0;
        if (lane < 8) myi = __ldg(&g_csrsrc[e + lane]);
        #pragma unroll
        for (int j = 0; j < 8; j++) {
            int s = __shfl_sync(0xFFFFFFFFu, myi, j);
            float2 t = __half22float2(*reinterpret_cast<const __half2*>(&hs[(size_t)s * D_OUT + col]));
            acc.x += t.x;
            acc.y += t.y;
        }
    }
    for (; e < end; e++) {
        int s = __ldg(&g_csrsrc[e]);
        float2 t = __half22float2(*reinterpret_cast<const __half2*>(&hs[(size_t)s * D_OUT + col]));
        acc.x += t.x; acc.y += t.y;
    }
    float s = dinv[v];
    float2 bb = *reinterpret_cast<const float2*>(&b2[col]);
    float2 r = make_float2(fmaf(acc.x, s, bb.x), fmaf(acc.y, s, bb.y));
    *reinterpret_cast<float2*>(&out[(size_t)v * D_OUT + col]) = r;
}

// ================= launch =================
extern "C" void kernel_launch(void* const* d_in, const int* in_sizes, int n_in,
                              void* d_out, int out_size)
{
    const float* x  = (const float*)d_in[0];
    const int*   ei = (const int*)  d_in[1];
    const float* W1 = (const float*)d_in[2];
    const float* b1 = (const float*)d_in[3];
    const float* W2 = (const float*)d_in[4];
    const float* b2 = (const float*)d_in[5];
    float* out = (float*)d_out;

    const int M = in_sizes[0] / D_IN;
    const int E = in_sizes[1] / 2;
    const int* src = ei;
    const int* dst = ei + E;

    __half *p_h1s, *p_agg1, *p_h2s;
    float *p_dinv;
    int *p_deg, *p_tilesum;
    cudaGetSymbolAddress((void**)&p_h1s,     g_h1s);
    cudaGetSymbolAddress((void**)&p_agg1,    g_agg1);
    cudaGetSymbolAddress((void**)&p_h2s,     g_h2s);
    cudaGetSymbolAddress((void**)&p_dinv,    g_dinv);
    cudaGetSymbolAddress((void**)&p_deg,     g_deg);
    cudaGetSymbolAddress((void**)&p_tilesum, g_tilesum);

    static cudaStream_t s2 = nullptr;
    static cudaEvent_t evFork = nullptr, evJoin = nullptr;
    if (s2 == nullptr) {
        cudaStreamCreateWithFlags(&s2, cudaStreamNonBlocking);
        cudaEventCreateWithFlags(&evFork, cudaEventDisableTiming);
        cudaEventCreateWithFlags(&evJoin, cudaEventDisableTiming);
    }

    const int T = 256;
    const int smem1 = (128 * 68 + 64 * 136) * 4;   // 69632
    const int smem2 = (128 * 68 + 64 * 72) * 4;    // 53248
    cudaFuncSetAttribute(gemm1_kernel,
                         cudaFuncAttributeMaxDynamicSharedMemorySize, smem1);
    cudaFuncSetAttribute(gemm2_kernel,
                         cudaFuncAttributeMaxDynamicSharedMemorySize, smem2);

    const int ntiles = (M + SCAN_TILE - 1) / SCAN_TILE;
    const int nblk = (M + 127) / 128;
    const int gblk = (M + 7) / 8;

    // ---- fork: CSR chain on s2, GEMM1 on main ----
    cudaEventRecord(evFork, 0);
    cudaStreamWaitEvent(s2, evFork, 0);

    cudaMemsetAsync(p_deg, 0, (size_t)M * sizeof(int), s2);
    cudaMemsetAsync(p_tilesum, 0, (size_t)MAX_TILES * sizeof(int), s2);
    deg_kernel<<<(E + T - 1) / T, T, 0, s2>>>(dst, E);
    scan_fused_kernel<<<ntiles, 256, 0, s2>>>(M);
    fill_kernel<<<(E + T - 1) / T, T, 0, s2>>>(src, dst, E);
    cudaEventRecord(evJoin, s2);

    // main: layer-1 GEMM (fp16 mma; no dinv dependency)
    gemm1_kernel<<<nblk, 256, smem1>>>(x, W1, p_h1s, M);

    cudaStreamWaitEvent(0, evJoin, 0);

    // pull-aggregate (fp32 accum, fp16 out)
    gather128_kernel<<<gblk, 256>>>(p_h1s, p_dinv, p_agg1, M);

    // layer-2 GEMM (fp16 mma, fused relu staging)
    gemm2_kernel<<<nblk, 256, smem2>>>(p_agg1, W2, p_dinv, b1, p_h2s, M);

    // final pull-aggregate + bias -> out
    gather64_out_kernel<<<gblk, 256>>>(p_h2s, p_dinv, b2, out, M);
}